// round 3
// baseline (speedup 1.0000x reference)
#include <cuda_runtime.h>
#include <cstdint>

// HardNetLoss via legacy mma.sync int8 (sm_80 PTX, valid on plain sm_103 target).
// S = A @ P^T computed exactly from a 2-digit int8 decomposition:
//   q = round(x*8192) = 128*hi + lo,  hi,lo in [-64,64]
//   S = (16384*HH + 128*(HL+LH) + LL) / 8192^2, int32-exact partial sums.
// d_ij = sqrt(2(1-s+eps)) is monotone decreasing in s -> min dist == max sim.

#define CNT 8192
#define KDIM 256
#define EPSV 1e-6f

#define TSTRIDE 272            // 256B row + 16B pad (conflict-free LDS)
#define TILE_BYTES (128 * TSTRIDE)
#define SM_AH 0
#define SM_BH (TILE_BYTES)
#define SM_AL (2 * TILE_BYTES)
#define SM_BL (3 * TILE_BYTES)
#define SM_SROW (4 * TILE_BYTES)
#define SM_SCOL (4 * TILE_BYTES + 512)
#define SM_TOTAL (4 * TILE_BYTES + 1024)

__device__ unsigned char g_hi[2 * CNT * KDIM];
__device__ unsigned char g_lo[2 * CNT * KDIM];
__device__ unsigned g_rowmax[CNT];
__device__ unsigned g_colmax[CNT];
__device__ float    g_diag[CNT];
__device__ float    g_partial[CNT / 256];

// order-preserving float<->uint for atomicMax
__device__ __forceinline__ unsigned encf(float f) {
    unsigned u = __float_as_uint(f);
    return (u & 0x80000000u) ? ~u : (u | 0x80000000u);
}
__device__ __forceinline__ float decf(unsigned e) {
    unsigned u = (e & 0x80000000u) ? (e & 0x7fffffffu) : ~e;
    return __uint_as_float(u);
}
__device__ __forceinline__ uint32_t smem_u32(const void* p) {
    uint32_t a;
    asm("{ .reg .u64 t; cvta.to.shared.u64 t, %1; cvt.u32.u64 %0, t; }" : "=r"(a) : "l"(p));
    return a;
}

__device__ __forceinline__ void cp_async16(uint32_t saddr, const void* gaddr) {
    asm volatile("cp.async.cg.shared.global [%0], [%1], 16;" :: "r"(saddr), "l"(gaddr) : "memory");
}

__device__ __forceinline__ void mma_s8(int* c, const uint32_t* a, const uint32_t* b) {
    asm volatile(
        "mma.sync.aligned.m16n8k32.row.col.s32.s8.s8.s32 "
        "{%0,%1,%2,%3}, {%4,%5,%6,%7}, {%8,%9}, {%0,%1,%2,%3};"
        : "+r"(c[0]), "+r"(c[1]), "+r"(c[2]), "+r"(c[3])
        : "r"(a[0]), "r"(a[1]), "r"(a[2]), "r"(a[3]), "r"(b[0]), "r"(b[1]));
}

// ---------------- kernels ----------------
__global__ void quant_kernel(const float* __restrict__ x) {
    int i = blockIdx.x * 256 + threadIdx.x;   // float4 index, 1048576 total
    float4 v = reinterpret_cast<const float4*>(x)[i];
    float q[4] = {v.x, v.y, v.z, v.w};
    uint32_t hw = 0, lw = 0;
#pragma unroll
    for (int j = 0; j < 4; j++) {
        float s = q[j] * 8192.0f;
        float h = rintf(s * 0.0078125f);      // s/128
        float l = rintf(s - 128.0f * h);
        hw |= ((uint32_t)((int)h & 0xff)) << (8 * j);
        lw |= ((uint32_t)((int)l & 0xff)) << (8 * j);
    }
    reinterpret_cast<uint32_t*>(g_hi)[i] = hw;
    reinterpret_cast<uint32_t*>(g_lo)[i] = lw;
}

__global__ void init_kernel() {
    int i = blockIdx.x * 256 + threadIdx.x;
    g_rowmax[i] = 0u;
    g_colmax[i] = 0u;
}

// one K-sweep of 128x128 tile: 8 k-chunks x 16 mma, accumulating into acc
__device__ __forceinline__ void mma_pass(const char* smem, uint32_t aOff, uint32_t bOff,
                                         int wm, int wn, int l, int (&acc)[16][4]) {
#pragma unroll
    for (int k0 = 0; k0 < KDIM; k0 += 32) {
        uint32_t a[4][4], b[4][2];
#pragma unroll
        for (int mt = 0; mt < 4; mt++) {
            const char* p = smem + aOff + (uint32_t)(wm * 64 + mt * 16 + (l >> 2)) * TSTRIDE
                          + k0 + (l & 3) * 4;
            a[mt][0] = *reinterpret_cast<const uint32_t*>(p);
            a[mt][1] = *reinterpret_cast<const uint32_t*>(p + 8 * TSTRIDE);
            a[mt][2] = *reinterpret_cast<const uint32_t*>(p + 16);
            a[mt][3] = *reinterpret_cast<const uint32_t*>(p + 8 * TSTRIDE + 16);
        }
#pragma unroll
        for (int nt = 0; nt < 4; nt++) {
            const char* p = smem + bOff + (uint32_t)(wn * 32 + nt * 8 + (l >> 2)) * TSTRIDE
                          + k0 + (l & 3) * 4;
            b[nt][0] = *reinterpret_cast<const uint32_t*>(p);
            b[nt][1] = *reinterpret_cast<const uint32_t*>(p + 16);
        }
#pragma unroll
        for (int mt = 0; mt < 4; mt++)
#pragma unroll
            for (int nt = 0; nt < 4; nt++)
                mma_s8(acc[mt * 4 + nt], a[mt], b[nt]);
    }
}

__global__ __launch_bounds__(256, 1)
void gemm_kernel() {
    extern __shared__ char smem[];
    const uint32_t sb = smem_u32(smem);
    const int tid = threadIdx.x;
    const int w = tid >> 5, l = tid & 31;
    const int wm = w >> 2, wn = w & 3;          // warp 64x32 tile in 128x128 CTA tile
    const int bx = blockIdx.x, by = blockIdx.y; // N tile (P rows), M tile (A rows)

    const char* Ahg = (const char*)g_hi + (size_t)(by * 128) * KDIM;
    const char* Bhg = (const char*)g_hi + (size_t)(CNT + bx * 128) * KDIM;
    const char* Alg = (const char*)g_lo + (size_t)(by * 128) * KDIM;
    const char* Blg = (const char*)g_lo + (size_t)(CNT + bx * 128) * KDIM;

    // group 0: hi tiles; group 1: lo tiles (16B chunks, 2048 per tile)
#pragma unroll
    for (int i = 0; i < 8; i++) {
        int idx = tid + i * 256;
        int row = idx >> 4, c16 = idx & 15;
        uint32_t so = (uint32_t)row * TSTRIDE + c16 * 16;
        cp_async16(sb + SM_AH + so, Ahg + row * KDIM + c16 * 16);
        cp_async16(sb + SM_BH + so, Bhg + row * KDIM + c16 * 16);
    }
    asm volatile("cp.async.commit_group;" ::: "memory");
#pragma unroll
    for (int i = 0; i < 8; i++) {
        int idx = tid + i * 256;
        int row = idx >> 4, c16 = idx & 15;
        uint32_t so = (uint32_t)row * TSTRIDE + c16 * 16;
        cp_async16(sb + SM_AL + so, Alg + row * KDIM + c16 * 16);
        cp_async16(sb + SM_BL + so, Blg + row * KDIM + c16 * 16);
    }
    asm volatile("cp.async.commit_group;" ::: "memory");

    float facc[16][4];
    int iacc[16][4];

    // pass HH (hi tiles only; overlaps lo-tile cp.async)
    asm volatile("cp.async.wait_group %0;" :: "n"(1) : "memory");
    __syncthreads();
#pragma unroll
    for (int t = 0; t < 16; t++)
#pragma unroll
        for (int e = 0; e < 4; e++) iacc[t][e] = 0;
    mma_pass(smem, SM_AH, SM_BH, wm, wn, l, iacc);
    const float C_HH = 16384.0f / 67108864.0f;
#pragma unroll
    for (int t = 0; t < 16; t++)
#pragma unroll
        for (int e = 0; e < 4; e++) facc[t][e] = (float)iacc[t][e] * C_HH;

    asm volatile("cp.async.wait_group %0;" :: "n"(0) : "memory");
    __syncthreads();

    // pass HL + LH (shared accumulator, same scale 128)
#pragma unroll
    for (int t = 0; t < 16; t++)
#pragma unroll
        for (int e = 0; e < 4; e++) iacc[t][e] = 0;
    mma_pass(smem, SM_AH, SM_BL, wm, wn, l, iacc);
    mma_pass(smem, SM_AL, SM_BH, wm, wn, l, iacc);
    const float C_M = 128.0f / 67108864.0f;
#pragma unroll
    for (int t = 0; t < 16; t++)
#pragma unroll
        for (int e = 0; e < 4; e++) facc[t][e] += (float)iacc[t][e] * C_M;

    // pass LL
#pragma unroll
    for (int t = 0; t < 16; t++)
#pragma unroll
        for (int e = 0; e < 4; e++) iacc[t][e] = 0;
    mma_pass(smem, SM_AL, SM_BL, wm, wn, l, iacc);
    const float C_LL = 1.0f / 67108864.0f;
#pragma unroll
    for (int t = 0; t < 16; t++)
#pragma unroll
        for (int e = 0; e < 4; e++) facc[t][e] += (float)iacc[t][e] * C_LL;

    // ---- fused epilogue: row/col max excl diagonal ----
    unsigned* srow = reinterpret_cast<unsigned*>(smem + SM_SROW);
    unsigned* scol = reinterpret_cast<unsigned*>(smem + SM_SCOL);
    if (tid < 128) srow[tid] = 0u; else scol[tid - 128] = 0u;
    __syncthreads();

    float rmax[8], cmax[8];
#pragma unroll
    for (int i = 0; i < 8; i++) { rmax[i] = -2.0f; cmax[i] = -2.0f; }

#pragma unroll
    for (int mt = 0; mt < 4; mt++)
#pragma unroll
        for (int nt = 0; nt < 4; nt++)
#pragma unroll
            for (int e = 0; e < 4; e++) {
                int h = e >> 1, j = e & 1;
                int lr = wm * 64 + mt * 16 + (l >> 2) + h * 8;
                int lc = wn * 32 + nt * 8 + 2 * (l & 3) + j;
                float s = facc[mt * 4 + nt][e];
                if (by * 128 + lr == bx * 128 + lc) {
                    g_diag[by * 128 + lr] = s;   // unique writer
                    s = -2.0f;
                }
                rmax[mt * 2 + h] = fmaxf(rmax[mt * 2 + h], s);
                cmax[nt * 2 + j] = fmaxf(cmax[nt * 2 + j], s);
            }

    // rows: reduce across the 4 lanes of a quad (same row, different cols)
#pragma unroll
    for (int st = 1; st <= 2; st <<= 1)
#pragma unroll
        for (int i = 0; i < 8; i++)
            rmax[i] = fmaxf(rmax[i], __shfl_xor_sync(0xffffffffu, rmax[i], st));
    if ((l & 3) == 0) {
#pragma unroll
        for (int mt = 0; mt < 4; mt++)
#pragma unroll
            for (int h = 0; h < 2; h++)
                atomicMax(&srow[wm * 64 + mt * 16 + (l >> 2) + h * 8], encf(rmax[mt * 2 + h]));
    }
    // cols: reduce across lanes sharing (l&3) (same col, different rows)
#pragma unroll
    for (int st = 4; st <= 16; st <<= 1)
#pragma unroll
        for (int i = 0; i < 8; i++)
            cmax[i] = fmaxf(cmax[i], __shfl_xor_sync(0xffffffffu, cmax[i], st));
    if (l < 4) {
#pragma unroll
        for (int nt = 0; nt < 4; nt++)
#pragma unroll
            for (int j = 0; j < 2; j++)
                atomicMax(&scol[wn * 32 + nt * 8 + 2 * l + j], encf(cmax[nt * 2 + j]));
    }
    __syncthreads();
    if (tid < 128) atomicMax(&g_rowmax[by * 128 + tid], srow[tid]);
    else           atomicMax(&g_colmax[bx * 128 + tid - 128], scol[tid - 128]);
}

__global__ void finish_kernel() {
    __shared__ float red[256];
    int i = blockIdx.x * 256 + threadIdx.x;
    float smax = fmaxf(decf(g_rowmax[i]), decf(g_colmax[i]));
    float neg = sqrtf((1.0f - smax + EPSV) * 2.0f);
    float pos = sqrtf((1.0f - g_diag[i] + EPSV) * 2.0f);
    float t = fmaxf(1.0f - neg + pos, 0.0f);
    red[threadIdx.x] = t;
    __syncthreads();
#pragma unroll
    for (int s = 128; s > 0; s >>= 1) {
        if (threadIdx.x < s) red[threadIdx.x] += red[threadIdx.x + s];
        __syncthreads();
    }
    if (threadIdx.x == 0) g_partial[blockIdx.x] = red[0];
}

__global__ void final_kernel(float* __restrict__ out) {
    if (threadIdx.x == 0) {
        float s = 0.0f;
        for (int i = 0; i < CNT / 256; i++) s += g_partial[i];
        out[0] = s / (float)CNT;
    }
}

extern "C" void kernel_launch(void* const* d_in, const int* in_sizes, int n_in,
                              void* d_out, int out_size) {
    (void)in_sizes; (void)n_in; (void)out_size;
    const float* x = (const float*)d_in[0];
    float* out = (float*)d_out;

    cudaFuncSetAttribute((const void*)gemm_kernel,
                         cudaFuncAttributeMaxDynamicSharedMemorySize, SM_TOTAL);

    quant_kernel<<<(2 * CNT * KDIM / 4) / 256, 256>>>(x);
    init_kernel<<<CNT / 256, 256>>>();
    dim3 grid(CNT / 128, CNT / 128);  // (64, 64)
    gemm_kernel<<<grid, 256, SM_TOTAL>>>();
    finish_kernel<<<CNT / 256, 256>>>();
    final_kernel<<<1, 32>>>(out);
}

// round 5
// speedup vs baseline: 2.5998x; 2.5998x over previous
#include <cuda_runtime.h>
#include <cuda_bf16.h>
#include <cstdint>

// HardNetLoss, screen-then-fix:
//   1 int8 legacy-mma screening GEMM (data-scaled) + bf16 dump of S~,
//   scan S~ for candidates within margin of screened row/col maxes,
//   exact fp32 dot fix of candidates, exact diagonal, tiny finish.

#define CNT 8192
#define KDIM 256
#define EPSV 1e-6f
#define MARGIN_C 0.05f

#define TSTRIDE 272
#define TILE_BYTES (128 * TSTRIDE)        // 34816
#define SM_SROW (2 * TILE_BYTES)
#define SM_SCOL (2 * TILE_BYTES + 512)
#define SM_TOTAL (2 * TILE_BYTES + 1024)  // 70656

#define LIST_CAP 2048

__device__ unsigned char g_q[2 * CNT * KDIM];          // int8 digits
__device__ __nv_bfloat16 g_S[(size_t)CNT * CNT];       // 128 MiB screened S~
__device__ unsigned g_srow[CNT], g_scol[CNT];          // screened maxes (encoded)
__device__ unsigned g_erow[CNT], g_ecol[CNT];          // exact maxes (encoded)
__device__ float    g_diag[CNT];
__device__ float    g_partial[CNT / 256];
__device__ unsigned g_maxabs;                          // bits of positive float
__device__ float    g_scale, g_inv2;

__device__ __forceinline__ unsigned encf(float f) {
    unsigned u = __float_as_uint(f);
    return (u & 0x80000000u) ? ~u : (u | 0x80000000u);
}
__device__ __forceinline__ float decf(unsigned e) {
    unsigned u = (e & 0x80000000u) ? (e & 0x7fffffffu) : ~e;
    return __uint_as_float(u);
}
__device__ __forceinline__ uint32_t smem_u32(const void* p) {
    uint32_t a;
    asm("{ .reg .u64 t; cvta.to.shared.u64 t, %1; cvt.u32.u64 %0, t; }" : "=r"(a) : "l"(p));
    return a;
}
__device__ __forceinline__ void cp_async16(uint32_t saddr, const void* gaddr) {
    asm volatile("cp.async.cg.shared.global [%0], [%1], 16;" :: "r"(saddr), "l"(gaddr) : "memory");
}
__device__ __forceinline__ void mma_s8(int* c, const uint32_t* a, const uint32_t* b) {
    asm volatile(
        "mma.sync.aligned.m16n8k32.row.col.s32.s8.s8.s32 "
        "{%0,%1,%2,%3}, {%4,%5,%6,%7}, {%8,%9}, {%0,%1,%2,%3};"
        : "+r"(c[0]), "+r"(c[1]), "+r"(c[2]), "+r"(c[3])
        : "r"(a[0]), "r"(a[1]), "r"(a[2]), "r"(a[3]), "r"(b[0]), "r"(b[1]));
}

// ---------------- prep ----------------
__global__ void maxabs_kernel(const float* __restrict__ x) {
    __shared__ float red[8];
    const float4* X4 = reinterpret_cast<const float4*>(x);
    int i = blockIdx.x * 256 + threadIdx.x;
    float m = 0.0f;
#pragma unroll
    for (int t = 0; t < 4; t++) {
        float4 v = X4[i + t * 262144];
        m = fmaxf(m, fmaxf(fmaxf(fabsf(v.x), fabsf(v.y)), fmaxf(fabsf(v.z), fabsf(v.w))));
    }
#pragma unroll
    for (int st = 16; st; st >>= 1) m = fmaxf(m, __shfl_xor_sync(~0u, m, st));
    if ((threadIdx.x & 31) == 0) red[threadIdx.x >> 5] = m;
    __syncthreads();
    if (threadIdx.x < 8) {
        m = red[threadIdx.x];
#pragma unroll
        for (int st = 4; st; st >>= 1) m = fmaxf(m, __shfl_xor_sync(0xffu, m, st));
        if (threadIdx.x == 0) atomicMax(&g_maxabs, __float_as_uint(m));
    }
}

__global__ void prep_kernel() {
    float ma = __uint_as_float(g_maxabs);
    float sc = 126.5f / ma;
    g_scale = sc;
    g_inv2 = 1.0f / (sc * sc);
}

__global__ void quant_kernel(const float* __restrict__ x) {
    int i = blockIdx.x * 256 + threadIdx.x;
    float sc = g_scale;
    float4 v = reinterpret_cast<const float4*>(x)[i];
    float q[4] = {v.x, v.y, v.z, v.w};
    uint32_t w = 0;
#pragma unroll
    for (int j = 0; j < 4; j++)
        w |= ((uint32_t)((int)rintf(q[j] * sc) & 0xff)) << (8 * j);
    reinterpret_cast<uint32_t*>(g_q)[i] = w;
}

__global__ void init_kernel() {
    int i = blockIdx.x * 256 + threadIdx.x;
    g_srow[i] = 0u; g_scol[i] = 0u;
    g_erow[i] = 0u; g_ecol[i] = 0u;
}

// ---------------- screening GEMM (single int8 pass) ----------------
__global__ __launch_bounds__(256, 2)
void gemm_screen() {
    extern __shared__ char smem[];
    const uint32_t sb = smem_u32(smem);
    const int tid = threadIdx.x;
    const int w = tid >> 5, l = tid & 31;
    const int wm = w >> 2, wn = w & 3;
    const int bx = blockIdx.x, by = blockIdx.y;

    const char* Ag = (const char*)g_q + (size_t)(by * 128) * KDIM;
    const char* Bg = (const char*)g_q + (size_t)(CNT + bx * 128) * KDIM;

#pragma unroll
    for (int i = 0; i < 8; i++) {
        int idx = tid + i * 256;
        int row = idx >> 4, c16 = idx & 15;
        uint32_t so = (uint32_t)row * TSTRIDE + c16 * 16;
        cp_async16(sb + so, Ag + row * KDIM + c16 * 16);
        cp_async16(sb + TILE_BYTES + so, Bg + row * KDIM + c16 * 16);
    }
    asm volatile("cp.async.commit_group;" ::: "memory");
    asm volatile("cp.async.wait_group 0;" ::: "memory");
    __syncthreads();

    int acc[16][4];
#pragma unroll
    for (int t = 0; t < 16; t++)
#pragma unroll
        for (int e = 0; e < 4; e++) acc[t][e] = 0;

#pragma unroll
    for (int k0 = 0; k0 < KDIM; k0 += 32) {
        uint32_t a[4][4], b[4][2];
#pragma unroll
        for (int mt = 0; mt < 4; mt++) {
            const char* p = smem + (uint32_t)(wm * 64 + mt * 16 + (l >> 2)) * TSTRIDE
                          + k0 + (l & 3) * 4;
            a[mt][0] = *reinterpret_cast<const uint32_t*>(p);
            a[mt][1] = *reinterpret_cast<const uint32_t*>(p + 8 * TSTRIDE);
            a[mt][2] = *reinterpret_cast<const uint32_t*>(p + 16);
            a[mt][3] = *reinterpret_cast<const uint32_t*>(p + 8 * TSTRIDE + 16);
        }
#pragma unroll
        for (int nt = 0; nt < 4; nt++) {
            const char* p = smem + TILE_BYTES + (uint32_t)(wn * 32 + nt * 8 + (l >> 2)) * TSTRIDE
                          + k0 + (l & 3) * 4;
            b[nt][0] = *reinterpret_cast<const uint32_t*>(p);
            b[nt][1] = *reinterpret_cast<const uint32_t*>(p + 16);
        }
#pragma unroll
        for (int mt = 0; mt < 4; mt++)
#pragma unroll
            for (int nt = 0; nt < 4; nt++)
                mma_s8(acc[mt * 4 + nt], a[mt], b[nt]);
    }

    // epilogue: store S~ bf16 + fused screened row/col max (excl diag)
    unsigned* srow = reinterpret_cast<unsigned*>(smem + SM_SROW);
    unsigned* scol = reinterpret_cast<unsigned*>(smem + SM_SCOL);
    __syncthreads();
    if (tid < 128) srow[tid] = 0u; else scol[tid - 128] = 0u;
    __syncthreads();

    const float inv2 = g_inv2;
    float rmax[8], cmax[8];
#pragma unroll
    for (int i = 0; i < 8; i++) { rmax[i] = -2.0f; cmax[i] = -2.0f; }

#pragma unroll
    for (int mt = 0; mt < 4; mt++)
#pragma unroll
        for (int nt = 0; nt < 4; nt++) {
#pragma unroll
            for (int h = 0; h < 2; h++) {
                int lr = wm * 64 + mt * 16 + (l >> 2) + h * 8;
                int lc = wn * 32 + nt * 8 + 2 * (l & 3);
                float s0 = (float)acc[mt * 4 + nt][2 * h + 0] * inv2;
                float s1 = (float)acc[mt * 4 + nt][2 * h + 1] * inv2;
                // store pair
                __nv_bfloat162 bp;
                bp.x = __float2bfloat16_rn(s0);
                bp.y = __float2bfloat16_rn(s1);
                *reinterpret_cast<__nv_bfloat162*>(
                    g_S + (size_t)(by * 128 + lr) * CNT + bx * 128 + lc) = bp;
                // max with diag exclusion
                if (by * 128 + lr == bx * 128 + lc) s0 = -2.0f;
                if (by * 128 + lr == bx * 128 + lc + 1) s1 = -2.0f;
                rmax[mt * 2 + h] = fmaxf(rmax[mt * 2 + h], fmaxf(s0, s1));
                cmax[nt * 2 + 0] = fmaxf(cmax[nt * 2 + 0], s0);
                cmax[nt * 2 + 1] = fmaxf(cmax[nt * 2 + 1], s1);
            }
        }

#pragma unroll
    for (int st = 1; st <= 2; st <<= 1)
#pragma unroll
        for (int i = 0; i < 8; i++)
            rmax[i] = fmaxf(rmax[i], __shfl_xor_sync(0xffffffffu, rmax[i], st));
    if ((l & 3) == 0) {
#pragma unroll
        for (int mt = 0; mt < 4; mt++)
#pragma unroll
            for (int h = 0; h < 2; h++)
                atomicMax(&srow[wm * 64 + mt * 16 + (l >> 2) + h * 8], encf(rmax[mt * 2 + h]));
    }
#pragma unroll
    for (int st = 4; st <= 16; st <<= 1)
#pragma unroll
        for (int i = 0; i < 8; i++)
            cmax[i] = fmaxf(cmax[i], __shfl_xor_sync(0xffffffffu, cmax[i], st));
    if (l < 4) {
#pragma unroll
        for (int nt = 0; nt < 4; nt++)
#pragma unroll
            for (int j = 0; j < 2; j++)
                atomicMax(&scol[wn * 32 + nt * 8 + 2 * l + j], encf(cmax[nt * 2 + j]));
    }
    __syncthreads();
    if (tid < 128) atomicMax(&g_srow[by * 128 + tid], srow[tid]);
    else           atomicMax(&g_scol[bx * 128 + tid - 128], scol[tid - 128]);
}

// ---------------- scan + exact fix ----------------
#define RPB 4
__global__ __launch_bounds__(256)
void scan_fix(const float* __restrict__ x) {
    __shared__ float thrC[CNT];         // 32 KB
    __shared__ unsigned list[LIST_CAP]; // 8 KB
    __shared__ int cnt;
    const int tid = threadIdx.x;

    for (int j = tid; j < CNT; j += 256) thrC[j] = decf(g_scol[j]) - MARGIN_C;
    if (tid == 0) cnt = 0;
    __syncthreads();

    const int row0 = blockIdx.x * RPB;
    for (int r = 0; r < RPB; r++) {
        const int row = row0 + r;
        const float thrR = decf(g_srow[row]) - MARGIN_C;
        const uint4* rp = reinterpret_cast<const uint4*>(g_S + (size_t)row * CNT);
        for (int k = tid; k < CNT / 8; k += 256) {
            uint4 v = rp[k];
            unsigned wv[4] = {v.x, v.y, v.z, v.w};
            int jb = k * 8;
#pragma unroll
            for (int q2 = 0; q2 < 4; q2++) {
                __nv_bfloat162 b2 = *reinterpret_cast<__nv_bfloat162*>(&wv[q2]);
                float s0 = __bfloat162float(b2.x);
                float s1 = __bfloat162float(b2.y);
                int j0 = jb + q2 * 2, j1 = j0 + 1;
                unsigned f0 = ((s0 >= thrR) ? 2u : 0u) | ((s0 >= thrC[j0]) ? 1u : 0u);
                if (f0 && j0 != row) {
                    int id = atomicAdd(&cnt, 1);
                    if (id < LIST_CAP) list[id] = ((unsigned)j0 << 4) | ((unsigned)r << 2) | f0;
                }
                unsigned f1 = ((s1 >= thrR) ? 2u : 0u) | ((s1 >= thrC[j1]) ? 1u : 0u);
                if (f1 && j1 != row) {
                    int id = atomicAdd(&cnt, 1);
                    if (id < LIST_CAP) list[id] = ((unsigned)j1 << 4) | ((unsigned)r << 2) | f1;
                }
            }
        }
    }
    __syncthreads();

    const int m = min(cnt, LIST_CAP);
    const int wid = tid >> 5, lane = tid & 31;
    for (int e = wid; e < m; e += 8) {
        unsigned ent = list[e];
        int j = ent >> 4, r = (ent >> 2) & 3;
        int row = row0 + r;
        const float4* ap = reinterpret_cast<const float4*>(x + (size_t)row * KDIM);
        const float4* pp = reinterpret_cast<const float4*>(x + (size_t)(CNT + j) * KDIM);
        float sum = 0.0f;
#pragma unroll
        for (int t = 0; t < 2; t++) {
            float4 a = ap[lane * 2 + t], p = pp[lane * 2 + t];
            sum += a.x * p.x + a.y * p.y + a.z * p.z + a.w * p.w;
        }
#pragma unroll
        for (int st = 16; st; st >>= 1) sum += __shfl_xor_sync(~0u, sum, st);
        if (lane == 0) {
            if (ent & 2u) atomicMax(&g_erow[row], encf(sum));
            if (ent & 1u) atomicMax(&g_ecol[j], encf(sum));
        }
    }
}

__global__ void diag_kernel(const float* __restrict__ x) {
    int gw = (blockIdx.x * blockDim.x + threadIdx.x) >> 5;
    int lane = threadIdx.x & 31;
    const float4* ap = reinterpret_cast<const float4*>(x + (size_t)gw * KDIM);
    const float4* pp = reinterpret_cast<const float4*>(x + (size_t)(CNT + gw) * KDIM);
    float sum = 0.0f;
#pragma unroll
    for (int t = 0; t < 2; t++) {
        float4 a = ap[lane * 2 + t], p = pp[lane * 2 + t];
        sum += a.x * p.x + a.y * p.y + a.z * p.z + a.w * p.w;
    }
#pragma unroll
    for (int st = 16; st; st >>= 1) sum += __shfl_xor_sync(~0u, sum, st);
    if (lane == 0) g_diag[gw] = sum;
}

__global__ void finish_kernel() {
    __shared__ float red[256];
    int i = blockIdx.x * 256 + threadIdx.x;
    float smax = fmaxf(decf(g_erow[i]), decf(g_ecol[i]));
    float neg = sqrtf((1.0f - smax + EPSV) * 2.0f);
    float pos = sqrtf((1.0f - g_diag[i] + EPSV) * 2.0f);
    float t = fmaxf(1.0f - neg + pos, 0.0f);
    red[threadIdx.x] = t;
    __syncthreads();
#pragma unroll
    for (int s = 128; s > 0; s >>= 1) {
        if (threadIdx.x < s) red[threadIdx.x] += red[threadIdx.x + s];
        __syncthreads();
    }
    if (threadIdx.x == 0) g_partial[blockIdx.x] = red[0];
}

__global__ void final_kernel(float* __restrict__ out) {
    if (threadIdx.x == 0) {
        float s = 0.0f;
        for (int i = 0; i < CNT / 256; i++) s += g_partial[i];
        out[0] = s / (float)CNT;
    }
}

extern "C" void kernel_launch(void* const* d_in, const int* in_sizes, int n_in,
                              void* d_out, int out_size) {
    (void)in_sizes; (void)n_in; (void)out_size;
    const float* x = (const float*)d_in[0];
    float* out = (float*)d_out;

    cudaFuncSetAttribute((const void*)gemm_screen,
                         cudaFuncAttributeMaxDynamicSharedMemorySize, SM_TOTAL);

    maxabs_kernel<<<1024, 256>>>(x);
    prep_kernel<<<1, 1>>>();
    quant_kernel<<<2 * CNT * KDIM / 4 / 256, 256>>>(x);
    init_kernel<<<CNT / 256, 256>>>();
    dim3 grid(CNT / 128, CNT / 128);
    gemm_screen<<<grid, 256, SM_TOTAL>>>();
    scan_fix<<<CNT / RPB, 256>>>(x);
    diag_kernel<<<CNT * 32 / 256, 256>>>(x);
    finish_kernel<<<CNT / 256, 256>>>();
    final_kernel<<<1, 32>>>(out);
}